// round 12
// baseline (speedup 1.0000x reference)
#include <cuda_runtime.h>
#include <cuda_fp16.h>

// Geometry constants (match reference)
#define HN 512
#define WN 512
#define NA 720
#define ND 725
#define NT 768
#define PW 516                  // 512 + 2-px zero border each side (multiple of 4)
#define OFF 2
#define TPR (PW / 4)            // 129 tiles per row
#define PAD_ELEMS (PW * PW)

typedef unsigned long long ull;

// Quad layout (column pairs): element (v,u) packs the 2x2 bilinear footprint
//   .x = (I[v][u],   I[v+1][u])    (left column,  half2)
//   .y = (I[v][u+1], I[v+1][u+1])  (right column, half2)
// Storage is 4x4 TILED: one 128B cache line = a 4x4 (v,u) block of quads, so a
// warp's ~7x9 sampling footprint touches ~7 lines instead of ~10-15.
__device__ uint2 g_quadP[PAD_ELEMS];
__device__ uint2 g_quadT[PAD_ELEMS];

__device__ __forceinline__ int tiled_idx(int vi, int ui) {
    return ((vi >> 2) * TPR + (ui >> 2)) * 16 + ((vi & 3) << 2) + (ui & 3);
}

__device__ __forceinline__ unsigned pack_h2(float lo, float hi) {
    __half2 h = __floats2half2_rn(lo, hi);
    return *reinterpret_cast<unsigned*>(&h);
}

// ---- packed f32x2 helpers (sm_103a) ----
__device__ __forceinline__ ull pk2(float lo, float hi) {
    ull r; asm("mov.b64 %0, {%1, %2};" : "=l"(r) : "f"(lo), "f"(hi)); return r;
}
__device__ __forceinline__ void upk2(float& lo, float& hi, ull v) {
    asm("mov.b64 {%0, %1}, %2;" : "=f"(lo), "=f"(hi) : "l"(v));
}
__device__ __forceinline__ ull fma2(ull a, ull b, ull c) {
    ull r; asm("fma.rn.f32x2 %0, %1, %2, %3;" : "=l"(r) : "l"(a), "l"(b), "l"(c)); return r;
}
__device__ __forceinline__ ull add2(ull a, ull b) {
    ull r; asm("add.rn.f32x2 %0, %1, %2;" : "=l"(r) : "l"(a), "l"(b)); return r;
}

__device__ __forceinline__ float padval(const float* __restrict__ x,
                                        const float* __restrict__ reco,
                                        int v, int u) {
    v -= OFF; u -= OFF;
    if ((unsigned)v < (unsigned)HN && (unsigned)u < (unsigned)WN) {
        int s = v * WN + u;
        return x[s] + reco[s];
    }
    return 0.0f;
}

__global__ void prep_kernel(const float* __restrict__ x,
                            const float* __restrict__ reco,
                            float* __restrict__ out_reco) {
    int i = blockIdx.x * blockDim.x + threadIdx.x;
    if (i >= PAD_ELEMS) return;
    int r = i / PW;
    int q = i - r * PW;
    int ti = tiled_idx(r, q);

    float a00 = padval(x, reco, r,     q);
    float a01 = padval(x, reco, r,     q + 1);
    float a10 = padval(x, reco, r + 1, q);
    float a11 = padval(x, reco, r + 1, q + 1);
    uint2 qp;
    qp.x = pack_h2(a00, a10);
    qp.y = pack_h2(a01, a11);
    g_quadP[ti] = qp;

    float b00 = padval(x, reco, q,     r);
    float b01 = padval(x, reco, q + 1, r);
    float b10 = padval(x, reco, q,     r + 1);
    float b11 = padval(x, reco, q + 1, r + 1);
    uint2 qt;
    qt.x = pack_h2(b00, b10);
    qt.y = pack_h2(b01, b11);
    g_quadT[ti] = qt;

    if (i < HN * WN) out_reco[i] = reco[i];
}

// Warp tiling: each warp covers 8 detectors x 4 t-offsets.
//   lane = (m<<3) | j :  j = detector offset, m = t phase (stride 4).
// Block = 128 threads = 4 warps = 32 detectors, one angle per blockIdx.y.
__global__ void __launch_bounds__(128) proj_kernel(float* __restrict__ sino) {
    const int a    = blockIdx.y;
    const int tid  = threadIdx.x;
    const int warp = tid >> 5;
    const int lane = tid & 31;
    const int j    = lane & 7;
    const int m    = lane >> 3;

    const int d    = blockIdx.x * 32 + warp * 8 + j;
    const int de   = min(d, ND - 1);

    const float theta = (float)a * (float)(3.14159265358979323846 / 720.0);
    float sn, c;
    sincosf(theta, &sn, &c);

    const float s = (float)de - 362.0f;     // (ND-1)/2 = 362
    const float bx = fmaf(s, c, 255.5f);
    const float by = fmaf(s, sn, 255.5f);

    const uint2* __restrict__ buf;
    float bu, bv, du, dv;
    if (fabsf(sn) > fabsf(c)) {             // lane axis mostly vertical -> transpose
        buf = g_quadT; bu = by; du = c;  bv = bx; dv = -sn;
    } else {
        buf = g_quadP; bu = bx; du = -sn; bv = by; dv = c;
    }

    // Clip t so fu,fv in [-1, 512] (outside => contribution exactly 0).
    float t0, t1;
    {
        float inv = 1.0f / dv;              // |dv| >= sqrt(2)/2 by layout choice
        float ta = (-1.0f - bv) * inv;
        float tb = (512.0f - bv) * inv;
        t0 = fminf(ta, tb);
        t1 = fmaxf(ta, tb);
    }
    if (fabsf(du) > 1e-8f) {
        float inv = 1.0f / du;
        float ta = (-1.0f - bu) * inv;
        float tb = (512.0f - bu) * inv;
        t0 = fmaxf(t0, fminf(ta, tb));
        t1 = fminf(t1, fmaxf(ta, tb));
    } else if (bu <= -1.0f || bu >= 512.0f) {
        t0 = 1.0f; t1 = 0.0f;               // empty
    }

    // t_k = k - 383.5. (int) of an out-of-range float SATURATES on GPU; clamp
    // klo to NT so klo+m can never overflow.
    int klo = max(0,      (int)ceilf(t0 + 383.5f));
    klo = min(klo, NT);
    const int khi = min(NT - 1, (int)floorf(t1 + 383.5f));

    // packed coordinate state (u in low, v in high)
    const ull duv  = pk2(du, dv);
    const ull puv  = pk2(bu + (float)OFF, bv + (float)OFF);
    const float MAGIC  = 8388608.0f;        // 2^23
    const float MAGICH = 8388607.5f;
    const ull MAG2  = pk2(MAGICH, MAGICH);
    const ull NMAG2 = pk2(-MAGIC, -MAGIC);
    const ull NONE2 = pk2(-1.0f, -1.0f);
    const ull STEP2 = pk2(4.0f, 4.0f);

    float tf0 = (float)(klo + m) - 383.5f;  // exact; stays exact under += 4.0
    ull tf2 = pk2(tf0, tf0);

    float acc = 0.0f;
    #pragma unroll 4
    for (int k = klo + m; k <= khi; k += 4) {
        ull fuv = fma2(tf2, duv, puv);
        ull fm2 = add2(fuv, MAG2);          // 2^23 + floor(f) in each half
        ull fl2 = add2(fm2, NMAG2);         // float floor
        ull w2  = fma2(fl2, NONE2, fuv);    // fractional parts (wu, wv)
        tf2 = add2(tf2, STEP2);

        float fmu, fmv; upk2(fmu, fmv, fm2);
        // Exact clipping + OFF folded into the base guarantees floor in
        // [0, 515]; low mantissa bits ARE the padded index.
        int ui = __float_as_int(fmu) & 0xFFF;
        int vi = __float_as_int(fmv) & 0xFFF;
        float wu, wv; upk2(wu, wv, w2);

        uint2 qd = __ldg(buf + tiled_idx(vi, ui));
        __half2 A = *reinterpret_cast<__half2*>(&qd.x);   // (top_l, bot_l)
        __half2 B = *reinterpret_cast<__half2*>(&qd.y);   // (top_r, bot_r)
        __half2 wu2 = __float2half2_rn(wu);
        __half2 res = __hfma2(__hsub2(B, A), wu2, A);     // (top, bottom)
        float2 rf = __half22float2(res);
        acc += fmaf(wv, rf.y - rf.x, rf.x);
    }

    // reduce the 4 t-phases of each detector
    acc += __shfl_xor_sync(0xffffffffu, acc, 8);
    acc += __shfl_xor_sync(0xffffffffu, acc, 16);

    if (m == 0 && d < ND) sino[a * ND + d] = acc;
}

extern "C" void kernel_launch(void* const* d_in, const int* in_sizes, int n_in,
                              void* d_out, int out_size) {
    const float* x    = (const float*)d_in[0];
    const float* reco = (const float*)d_in[1];
    float* out_sino = (float*)d_out;
    float* out_reco = (float*)d_out + NA * ND;

    prep_kernel<<<(PAD_ELEMS + 255) / 256, 256>>>(x, reco, out_reco);

    dim3 grid((ND + 31) / 32, NA);
    proj_kernel<<<grid, 128>>>(out_sino);
}

// round 13
// speedup vs baseline: 1.0864x; 1.0864x over previous
#include <cuda_runtime.h>
#include <cuda_fp16.h>

// Geometry constants (match reference)
#define HN 512
#define WN 512
#define NA 720
#define ND 725
#define NT 768
#define PW 516                  // 512 + 2-px zero border each side
#define OFF 2
#define PAD_ELEMS (PW * PW)

typedef unsigned long long ull;

// Quad layout (lerp-ready): element (v,u) packs the 2x2 bilinear footprint as
//   .x = A = (I[v][u],        I[v+1][u])          (left column, half2)
//   .y = D = (I[v][u+1]-I[v][u], I[v+1][u+1]-I[v+1][u])  (horizontal diffs)
// so the horizontal lerp is ONE hfma2: res = D*wu + A = (top, bottom).
__device__ uint2 g_quadP[PAD_ELEMS];
__device__ uint2 g_quadT[PAD_ELEMS];

__device__ __forceinline__ unsigned pack_h2(float lo, float hi) {
    __half2 h = __floats2half2_rn(lo, hi);
    return *reinterpret_cast<unsigned*>(&h);
}

// ---- packed f32x2 helpers (sm_103a) ----
__device__ __forceinline__ ull pk2(float lo, float hi) {
    ull r; asm("mov.b64 %0, {%1, %2};" : "=l"(r) : "f"(lo), "f"(hi)); return r;
}
__device__ __forceinline__ void upk2(float& lo, float& hi, ull v) {
    asm("mov.b64 {%0, %1}, %2;" : "=f"(lo), "=f"(hi) : "l"(v));
}
__device__ __forceinline__ ull fma2(ull a, ull b, ull c) {
    ull r; asm("fma.rn.f32x2 %0, %1, %2, %3;" : "=l"(r) : "l"(a), "l"(b), "l"(c)); return r;
}
__device__ __forceinline__ ull add2(ull a, ull b) {
    ull r; asm("add.rn.f32x2 %0, %1, %2;" : "=l"(r) : "l"(a), "l"(b)); return r;
}

__device__ __forceinline__ float padval(const float* __restrict__ x,
                                        const float* __restrict__ reco,
                                        int v, int u) {
    v -= OFF; u -= OFF;
    if ((unsigned)v < (unsigned)HN && (unsigned)u < (unsigned)WN) {
        int s = v * WN + u;
        return x[s] + reco[s];
    }
    return 0.0f;
}

__global__ void prep_kernel(const float* __restrict__ x,
                            const float* __restrict__ reco,
                            float* __restrict__ out_reco) {
    int i = blockIdx.x * blockDim.x + threadIdx.x;
    if (i >= PAD_ELEMS) return;
    int r = i / PW;
    int q = i - r * PW;

    float a00 = padval(x, reco, r,     q);
    float a01 = padval(x, reco, r,     q + 1);
    float a10 = padval(x, reco, r + 1, q);
    float a11 = padval(x, reco, r + 1, q + 1);
    uint2 qp;
    qp.x = pack_h2(a00, a10);
    qp.y = pack_h2(a01 - a00, a11 - a10);
    g_quadP[i] = qp;

    float b00 = padval(x, reco, q,     r);
    float b01 = padval(x, reco, q + 1, r);
    float b10 = padval(x, reco, q,     r + 1);
    float b11 = padval(x, reco, q + 1, r + 1);
    uint2 qt;
    qt.x = pack_h2(b00, b10);
    qt.y = pack_h2(b01 - b00, b11 - b10);
    g_quadT[i] = qt;

    if (i < HN * WN) out_reco[i] = reco[i];
}

// Warp tiling: each warp covers 8 detectors x 4 t-offsets.
//   lane = (m<<3) | j :  j = detector offset, m = t phase (stride 4).
// Block = 128 threads = 4 warps = 32 detectors, one angle per blockIdx.y.
__global__ void __launch_bounds__(128) proj_kernel(float* __restrict__ sino) {
    const int a    = blockIdx.y;
    const int tid  = threadIdx.x;
    const int warp = tid >> 5;
    const int lane = tid & 31;
    const int j    = lane & 7;
    const int m    = lane >> 3;

    const int d    = blockIdx.x * 32 + warp * 8 + j;
    const int de   = min(d, ND - 1);

    const float theta = (float)a * (float)(3.14159265358979323846 / 720.0);
    float sn, c;
    sincosf(theta, &sn, &c);

    const float s = (float)de - 362.0f;     // (ND-1)/2 = 362
    const float bx = fmaf(s, c, 255.5f);
    const float by = fmaf(s, sn, 255.5f);

    const uint2* __restrict__ buf;
    float bu, bv, du, dv;
    if (fabsf(sn) > fabsf(c)) {             // lane axis mostly vertical -> transpose
        buf = g_quadT; bu = by; du = c;  bv = bx; dv = -sn;
    } else {
        buf = g_quadP; bu = bx; du = -sn; bv = by; dv = c;
    }

    // Clip t so fu,fv in [-1, 512] (outside => contribution exactly 0).
    float t0, t1;
    {
        float inv = 1.0f / dv;              // |dv| >= sqrt(2)/2 by layout choice
        float ta = (-1.0f - bv) * inv;
        float tb = (512.0f - bv) * inv;
        t0 = fminf(ta, tb);
        t1 = fmaxf(ta, tb);
    }
    if (fabsf(du) > 1e-8f) {
        float inv = 1.0f / du;
        float ta = (-1.0f - bu) * inv;
        float tb = (512.0f - bu) * inv;
        t0 = fmaxf(t0, fminf(ta, tb));
        t1 = fminf(t1, fmaxf(ta, tb));
    } else if (bu <= -1.0f || bu >= 512.0f) {
        t0 = 1.0f; t1 = 0.0f;               // empty
    }

    // t_k = k - 383.5. (int) of an out-of-range float SATURATES on GPU; clamp
    // klo to NT so klo+m can never overflow.
    int klo = max(0,      (int)ceilf(t0 + 383.5f));
    klo = min(klo, NT);
    const int khi = min(NT - 1, (int)floorf(t1 + 383.5f));

    // packed coordinate state (u in low, v in high)
    const ull duv  = pk2(du, dv);
    const ull puv  = pk2(bu + (float)OFF, bv + (float)OFF);
    const float MAGIC  = 8388608.0f;        // 2^23
    const float MAGICH = 8388607.5f;
    const ull MAG2  = pk2(MAGICH, MAGICH);
    const ull NMAG2 = pk2(-MAGIC, -MAGIC);
    const ull NONE2 = pk2(-1.0f, -1.0f);
    const ull STEP2 = pk2(4.0f, 4.0f);
    // Magic-bits addressing: (0x4B000000+vi)*PW + (0x4B000000+ui) =
    //   vi*PW + ui + 0x4B000000*(PW+1); cancel the bias mod 2^32.
    const unsigned CADJ = (unsigned)(0u - 0x4B000000u * (unsigned)(PW + 1));

    float tf0 = (float)(klo + m) - 383.5f;  // exact; stays exact under += 4.0
    ull tf2 = pk2(tf0, tf0);

    float acc = 0.0f;
    #pragma unroll 4
    for (int k = klo + m; k <= khi; k += 4) {
        ull fuv = fma2(tf2, duv, puv);
        ull fm2 = add2(fuv, MAG2);          // 2^23 + floor(f) in each half
        ull fl2 = add2(fm2, NMAG2);         // float floor (exact)
        ull w2  = fma2(fl2, NONE2, fuv);    // fractional parts (wu, wv)
        tf2 = add2(tf2, STEP2);

        float fmu, fmv; upk2(fmu, fmv, fm2);
        unsigned idx = (unsigned)__float_as_int(fmv) * (unsigned)PW
                     + (unsigned)__float_as_int(fmu) + CADJ;
        float wu, wv; upk2(wu, wv, w2);

        uint2 qd = __ldg(buf + idx);
        __half2 A = *reinterpret_cast<__half2*>(&qd.x);   // (top_l, bot_l)
        __half2 D = *reinterpret_cast<__half2*>(&qd.y);   // horizontal diffs
        __half2 wu2 = __float2half2_rn(wu);
        __half2 res = __hfma2(D, wu2, A);                 // (top, bottom)
        float2 rf = __half22float2(res);
        acc += fmaf(wv, rf.y - rf.x, rf.x);
    }

    // reduce the 4 t-phases of each detector
    acc += __shfl_xor_sync(0xffffffffu, acc, 8);
    acc += __shfl_xor_sync(0xffffffffu, acc, 16);

    if (m == 0 && d < ND) sino[a * ND + d] = acc;
}

extern "C" void kernel_launch(void* const* d_in, const int* in_sizes, int n_in,
                              void* d_out, int out_size) {
    const float* x    = (const float*)d_in[0];
    const float* reco = (const float*)d_in[1];
    float* out_sino = (float*)d_out;
    float* out_reco = (float*)d_out + NA * ND;

    prep_kernel<<<(PAD_ELEMS + 255) / 256, 256>>>(x, reco, out_reco);

    dim3 grid((ND + 31) / 32, NA);
    proj_kernel<<<grid, 128>>>(out_sino);
}

// round 14
// speedup vs baseline: 1.3077x; 1.2037x over previous
#include <cuda_runtime.h>
#include <cuda_fp16.h>

// Geometry constants (match reference)
#define HN 512
#define WN 512
#define NA 720
#define NAH 360                 // angle pairs: a and a+360 (theta and theta+pi/2)
#define ND 725
#define NT 768
#define PW 516                  // 512 + 2-px zero border each side
#define OFF 2
#define PAD_ELEMS (PW * PW)

typedef unsigned long long ull;

// Padded fp32 image (zero border), built by prep0.
__device__ float g_img[PAD_ELEMS];

// Fused quad tables: one uint4 per (vi,ui) packs TWO lerp-ready quads:
//   .x = A  (primary):   (top_left, bottom_left)            half2
//   .y = D  (primary):   horizontal diffs                   half2
//   .z = A' (rot-pair):  quarter-rotated image quad         half2
//   .w = D' (rot-pair):  its horizontal diffs               half2
// such that BOTH evaluate with the same (wu, wv):
//   val = (A + D*wu).x + wv*((A + D*wu).y - (A + D*wu).x)
// g_arrP: primary = identity orientation; g_arrT: primary = transposed.
__device__ uint4 g_arrP[PAD_ELEMS];
__device__ uint4 g_arrT[PAD_ELEMS];

__device__ __forceinline__ unsigned pack_h2(float lo, float hi) {
    __half2 h = __floats2half2_rn(lo, hi);
    return *reinterpret_cast<unsigned*>(&h);
}

// ---- packed f32x2 helpers (sm_103a) ----
__device__ __forceinline__ ull pk2(float lo, float hi) {
    ull r; asm("mov.b64 %0, {%1, %2};" : "=l"(r) : "f"(lo), "f"(hi)); return r;
}
__device__ __forceinline__ void upk2(float& lo, float& hi, ull v) {
    asm("mov.b64 {%0, %1}, %2;" : "=f"(lo), "=f"(hi) : "l"(v));
}
__device__ __forceinline__ ull fma2(ull a, ull b, ull c) {
    ull r; asm("fma.rn.f32x2 %0, %1, %2, %3;" : "=l"(r) : "l"(a), "l"(b), "l"(c)); return r;
}
__device__ __forceinline__ ull add2(ull a, ull b) {
    ull r; asm("add.rn.f32x2 %0, %1, %2;" : "=l"(r) : "l"(a), "l"(b)); return r;
}

// prep0: padded image = x + reco (zero border), plus reco passthrough.
__global__ void prep0_kernel(const float* __restrict__ x,
                             const float* __restrict__ reco,
                             float* __restrict__ out_reco) {
    int i = blockIdx.x * blockDim.x + threadIdx.x;
    if (i >= PAD_ELEMS) return;
    int v = i / PW;
    int u = i - v * PW;
    float val = 0.0f;
    if (u >= OFF && u < OFF + WN && v >= OFF && v < OFF + HN) {
        int s = (v - OFF) * WN + (u - OFF);
        val = x[s] + reco[s];
    }
    g_img[i] = val;
    if (i < HN * WN) out_reco[i] = reco[i];
}

// Image fetch in unpadded coords, zero outside [-2,513] padded range.
__device__ __forceinline__ float IM(int v, int u) {
    unsigned vv = (unsigned)(v + OFF);
    unsigned uu = (unsigned)(u + OFF);
    return (vv < (unsigned)PW && uu < (unsigned)PW) ? g_img[vv * PW + uu] : 0.0f;
}

// prep1: build both fused quad tables.
// Primary (identity): quad over rows v0,v0+1 / cols u0,u0+1.
// Rot-pair for identity orientation: sample value = bilinear(I, X=511-fv, Y=fu):
//   A' = (I[u0][511-v0], I[u0][510-v0]); D' = (I[u0+1][511-v0]-A'.x, I[u0+1][510-v0]-A'.y)
// Rot-pair for transposed orientation: value = bilinear(I, X=511-fu, Y=fv):
//   A' = (I[v0][511-u0], I[v0+1][511-u0]); D' = (I[v0][510-u0]-A'.x, I[v0+1][510-u0]-A'.y)
__global__ void prep1_kernel() {
    int i = blockIdx.x * blockDim.x + threadIdx.x;
    if (i >= PAD_ELEMS) return;
    int vi = i / PW;
    int ui = i - vi * PW;
    int v0 = vi - OFF;
    int u0 = ui - OFF;

    // identity-orientation primary quad
    float a0 = IM(v0, u0),     a1 = IM(v0 + 1, u0);
    float b0 = IM(v0, u0 + 1), b1 = IM(v0 + 1, u0 + 1);
    // its rotation pair
    float q01 = IM(u0, 511 - v0),     q00 = IM(u0, 510 - v0);
    float q11 = IM(u0 + 1, 511 - v0), q10 = IM(u0 + 1, 510 - v0);
    uint4 P;
    P.x = pack_h2(a0, a1);
    P.y = pack_h2(b0 - a0, b1 - a1);
    P.z = pack_h2(q01, q00);
    P.w = pack_h2(q11 - q01, q10 - q00);
    g_arrP[i] = P;

    // transposed-orientation primary quad (IT[v][u] = I[u][v])
    float t0 = IM(u0, v0),     t1 = IM(u0, v0 + 1);
    float s0 = IM(u0 + 1, v0), s1 = IM(u0 + 1, v0 + 1);
    // its rotation pair
    float r0 = IM(v0, 511 - u0),     r1 = IM(v0 + 1, 511 - u0);
    float p0 = IM(v0, 510 - u0),     p1 = IM(v0 + 1, 510 - u0);
    uint4 T;
    T.x = pack_h2(t0, t1);
    T.y = pack_h2(s0 - t0, s1 - t1);
    T.z = pack_h2(r0, r1);
    T.w = pack_h2(p0 - r0, p1 - r1);
    g_arrT[i] = T;
}

// Warp tiling: each warp covers 8 detectors x 4 t-offsets; each thread
// produces TWO sinogram samples per loaded uint4: angle a and angle a+360.
__global__ void __launch_bounds__(128) proj_kernel(float* __restrict__ sino) {
    const int a    = blockIdx.y;          // 0..359, theta in [0, pi/2)
    const int tid  = threadIdx.x;
    const int warp = tid >> 5;
    const int lane = tid & 31;
    const int j    = lane & 7;
    const int m    = lane >> 3;

    const int d    = blockIdx.x * 32 + warp * 8 + j;
    const int de   = min(d, ND - 1);

    const float theta = (float)a * (float)(3.14159265358979323846 / 720.0);
    float sn, c;
    sincosf(theta, &sn, &c);

    const float s = (float)de - 362.0f;   // (ND-1)/2 = 362
    const float bx = fmaf(s, c, 255.5f);
    const float by = fmaf(s, sn, 255.5f);

    const uint4* __restrict__ buf;
    float bu, bv, du, dv;
    if (sn > c) {                         // theta > pi/4 -> transpose orientation
        buf = g_arrT; bu = by; du = c;  bv = bx; dv = -sn;
    } else {
        buf = g_arrP; bu = bx; du = -sn; bv = by; dv = c;
    }

    // Clip t so fu,fv in [-1, 512]. The rotation pair has EXACTLY the same
    // support (X = 511-f, Y = f map (-1,512) onto itself), so one clip serves both.
    float t0, t1;
    {
        float inv = 1.0f / dv;            // |dv| >= sqrt(2)/2 by orientation choice
        float ta = (-1.0f - bv) * inv;
        float tb = (512.0f - bv) * inv;
        t0 = fminf(ta, tb);
        t1 = fmaxf(ta, tb);
    }
    if (fabsf(du) > 1e-8f) {
        float inv = 1.0f / du;
        float ta = (-1.0f - bu) * inv;
        float tb = (512.0f - bu) * inv;
        t0 = fmaxf(t0, fminf(ta, tb));
        t1 = fminf(t1, fmaxf(ta, tb));
    } else if (bu <= -1.0f || bu >= 512.0f) {
        t0 = 1.0f; t1 = 0.0f;             // empty
    }

    // t_k = k - 383.5. Clamp klo (int-from-float saturates) so klo+m can't overflow.
    int klo = max(0,      (int)ceilf(t0 + 383.5f));
    klo = min(klo, NT);
    const int khi = min(NT - 1, (int)floorf(t1 + 383.5f));

    // packed coordinate state (u in low, v in high)
    const ull duv  = pk2(du, dv);
    const ull puv  = pk2(bu + (float)OFF, bv + (float)OFF);
    const float MAGIC  = 8388608.0f;      // 2^23
    const float MAGICH = 8388607.5f;
    const ull MAG2  = pk2(MAGICH, MAGICH);
    const ull NMAG2 = pk2(-MAGIC, -MAGIC);
    const ull NONE2 = pk2(-1.0f, -1.0f);
    const ull STEP2 = pk2(4.0f, 4.0f);
    // Magic-bits addressing: bias 0x4B000000*(PW+1) cancels mod 2^32.
    const unsigned CADJ = (unsigned)(0u - 0x4B000000u * (unsigned)(PW + 1));

    float tf0 = (float)(klo + m) - 383.5f;  // exact; stays exact under += 4.0
    ull tf2 = pk2(tf0, tf0);

    ull accP = pk2(0.0f, 0.0f);
    ull accQ = pk2(0.0f, 0.0f);
    #pragma unroll 4
    for (int k = klo + m; k <= khi; k += 4) {
        ull fuv = fma2(tf2, duv, puv);
        ull fm2 = add2(fuv, MAG2);        // 2^23 + floor(f) in each half
        ull fl2 = add2(fm2, NMAG2);       // float floor (exact)
        ull w2  = fma2(fl2, NONE2, fuv);  // fractional parts (wu, wv)
        tf2 = add2(tf2, STEP2);

        float fmu, fmv; upk2(fmu, fmv, fm2);
        unsigned idx = (unsigned)__float_as_int(fmv) * (unsigned)PW
                     + (unsigned)__float_as_int(fmu) + CADJ;
        float wu, wv; upk2(wu, wv, w2);

        uint4 qd = __ldg(buf + idx);      // ONE LDG.128 -> both angles' quads
        __half2 wu2 = __float2half2_rn(wu);
        __half2 resP = __hfma2(*reinterpret_cast<__half2*>(&qd.y), wu2,
                               *reinterpret_cast<__half2*>(&qd.x));
        __half2 resQ = __hfma2(*reinterpret_cast<__half2*>(&qd.w), wu2,
                               *reinterpret_cast<__half2*>(&qd.z));
        float2 rp = __half22float2(resP); // (top, bottom)
        float2 rq = __half22float2(resQ);
        ull WV2 = pk2(1.0f - wv, wv);
        accP = fma2(pk2(rp.x, rp.y), WV2, accP);
        accQ = fma2(pk2(rq.x, rq.y), WV2, accQ);
    }

    float pl, ph; upk2(pl, ph, accP);
    float ql, qh; upk2(ql, qh, accQ);
    float sp = pl + ph;
    float sq = ql + qh;

    // reduce the 4 t-phases of each detector
    sp += __shfl_xor_sync(0xffffffffu, sp, 8);
    sp += __shfl_xor_sync(0xffffffffu, sp, 16);
    sq += __shfl_xor_sync(0xffffffffu, sq, 8);
    sq += __shfl_xor_sync(0xffffffffu, sq, 16);

    if (m == 0 && d < ND) {
        sino[a * ND + d] = sp;
        sino[(a + NAH) * ND + d] = sq;
    }
}

extern "C" void kernel_launch(void* const* d_in, const int* in_sizes, int n_in,
                              void* d_out, int out_size) {
    const float* x    = (const float*)d_in[0];
    const float* reco = (const float*)d_in[1];
    float* out_sino = (float*)d_out;
    float* out_reco = (float*)d_out + NA * ND;

    const int nb = (PAD_ELEMS + 255) / 256;
    prep0_kernel<<<nb, 256>>>(x, reco, out_reco);
    prep1_kernel<<<nb, 256>>>();

    dim3 grid((ND + 31) / 32, NAH);
    proj_kernel<<<grid, 128>>>(out_sino);
}